// round 1
// baseline (speedup 1.0000x reference)
#include <cuda_runtime.h>

// Problem constants (fixed by the dataset problem):
//   values:         [16384, 2048] f32  (UNUSED except for shape)
//   kernel_weights: [6] f32
//   out:            [16384, 2046] f32  = tanh(broadcast(row))
#define BS      16384
#define L_OUT   2046
#define NKER    6

__device__ float g_row[L_OUT];

// log(std * sqrt(2*pi)) with std = 0.1
#define NEG_LOG_NORM 1.3836465597893728f
#define INV_STD      10.0f

__global__ void compute_row_kernel(const float* __restrict__ kw) {
    int col = blockIdx.x * blockDim.x + threadIdx.x;
    if (col >= L_OUT) return;

    const float means[NKER] = {0.0f, 0.2f, 0.4f, 0.6f, 0.8f, 1.0f};

    float pos = (float)col / (float)L_OUT;
    float acc = 0.0f;
#pragma unroll
    for (int k = 0; k < NKER; k++) {
        float w = 0.25f * tanhf(kw[k]);
        float z = (pos - means[k]) * INV_STD;
        float pdf = expf(-0.5f * z * z + NEG_LOG_NORM);
        acc = fmaf(w, pdf, acc);
    }
    g_row[col] = tanhf(acc);
}

// Each block: load row into smem once, then write 16 float4 per thread.
// Grid: 2046 blocks x 256 threads; 2046*256*16 float4 = 16384*2046 floats exactly.
#define TPB       256
#define F4_PER_T  16

__global__ void __launch_bounds__(TPB) broadcast_kernel(float4* __restrict__ out) {
    __shared__ float srow[L_OUT];
    for (int i = threadIdx.x; i < L_OUT; i += TPB)
        srow[i] = g_row[i];
    __syncthreads();

    int block_f4_base = blockIdx.x * (TPB * F4_PER_T);
#pragma unroll
    for (int k = 0; k < F4_PER_T; k++) {
        int j = block_f4_base + k * TPB + threadIdx.x;   // float4 index
        int e = j * 4;                                    // element index (< 2^26, fits int)
        int c0 = e % L_OUT;
        int c1 = c0 + 1; if (c1 >= L_OUT) c1 -= L_OUT;
        int c2 = c1 + 1; if (c2 >= L_OUT) c2 -= L_OUT;
        int c3 = c2 + 1; if (c3 >= L_OUT) c3 -= L_OUT;
        float4 v;
        v.x = srow[c0];
        v.y = srow[c1];
        v.z = srow[c2];
        v.w = srow[c3];
        out[j] = v;
    }
}

extern "C" void kernel_launch(void* const* d_in, const int* in_sizes, int n_in,
                              void* d_out, int out_size) {
    const float* kw = (const float*)d_in[1];   // kernel_weights [6]
    float4* out = (float4*)d_out;

    compute_row_kernel<<<(L_OUT + 1023) / 1024, 1024>>>(kw);

    int total_f4 = (BS * L_OUT) / 4;                 // 8,380,416
    int nblocks = total_f4 / (TPB * F4_PER_T);       // 2046 exactly
    broadcast_kernel<<<nblocks, TPB>>>(out);
}